// round 2
// baseline (speedup 1.0000x reference)
#include <cuda_runtime.h>
#include <math.h>

// mParametricLIF: x [N=128, T=64, D=4096] f32 -> spikes [N,T,D] f32.
// Per-(n,d) recurrence over t (elementwise in n,d; sequential in t):
//   m = lam*m + k*(x - v);  v += m;  s = (v >= th);  v = s ? 0 : v;  out = s
// k = sigmoid(tau_param[0]), lam = lamb[0], th = th[0].
//
// R2 changes vs R1 (42.7us kernel, DRAM 64%):
//  - block=128, grid=1024: wave balance 86.5% -> 98.8% over 148 SMs
//  - __ldcs streaming loads batched into buf[] (force MLP=8 per thread)
//  - __stcs streaming stores (write-once output, no L2 retention)

#ifndef TUNROLL
#define TUNROLL 8
#endif

__global__ __launch_bounds__(128) void mplif_kernel(
    const float4* __restrict__ x4,
    const float* __restrict__ tau_param,
    const float* __restrict__ lamb,
    const float* __restrict__ thr,
    float4* __restrict__ out4,
    int T, int DC /* D/4 */, int lanes /* N*DC */)
{
    int tid = blockIdx.x * blockDim.x + threadIdx.x;
    if (tid >= lanes) return;

    int n = tid / DC;
    int c = tid - n * DC;
    long base = (long)n * T * DC + c;

    const float k   = 1.0f / (1.0f + expf(-tau_param[0]));
    const float lam = lamb[0];
    const float th  = thr[0];

    float4 v = make_float4(0.f, 0.f, 0.f, 0.f);
    float4 m = make_float4(0.f, 0.f, 0.f, 0.f);

    float4 buf[TUNROLL];

    for (int t0 = 0; t0 < T; t0 += TUNROLL) {
        // Batch independent streaming loads first (MLP = TUNROLL LDG.128).
        #pragma unroll
        for (int j = 0; j < TUNROLL; j++) {
            buf[j] = __ldcs(&x4[base + (long)(t0 + j) * DC]);
        }
        // Serial recurrence on registers.
        #pragma unroll
        for (int j = 0; j < TUNROLL; j++) {
            float4 xv = buf[j];
            float4 s;

            m.x = lam * m.x + k * (xv.x - v.x); v.x += m.x;
            m.y = lam * m.y + k * (xv.y - v.y); v.y += m.y;
            m.z = lam * m.z + k * (xv.z - v.z); v.z += m.z;
            m.w = lam * m.w + k * (xv.w - v.w); v.w += m.w;

            s.x = (v.x >= th) ? 1.0f : 0.0f;
            s.y = (v.y >= th) ? 1.0f : 0.0f;
            s.z = (v.z >= th) ? 1.0f : 0.0f;
            s.w = (v.w >= th) ? 1.0f : 0.0f;

            v.x = (s.x != 0.0f) ? 0.0f : v.x;
            v.y = (s.y != 0.0f) ? 0.0f : v.y;
            v.z = (s.z != 0.0f) ? 0.0f : v.z;
            v.w = (s.w != 0.0f) ? 0.0f : v.w;

            __stcs(&out4[base + (long)(t0 + j) * DC], s);
        }
    }
}

extern "C" void kernel_launch(void* const* d_in, const int* in_sizes, int n_in,
                              void* d_out, int out_size)
{
    const float* x         = (const float*)d_in[0];
    const float* tau_param = (const float*)d_in[1];
    const float* lamb      = (const float*)d_in[2];
    const float* th        = (const float*)d_in[3];
    float* out             = (float*)d_out;

    const int N = 128, T = 64, D = 4096;
    const int DC = D / 4;
    const int lanes = N * DC;

    dim3 block(128);
    dim3 grid((lanes + block.x - 1) / block.x);  // 1024 blocks
    mplif_kernel<<<grid, block>>>((const float4*)x, tau_param, lamb, th,
                                  (float4*)out, T, DC, lanes);
}

// round 3
// speedup vs baseline: 1.0260x; 1.0260x over previous
#include <cuda_runtime.h>
#include <math.h>

// mParametricLIF: x [N=128, T=64, D=4096] f32 -> spikes [N,T,D] f32.
// Per-(n,d) recurrence over t (elementwise in n,d; sequential in t):
//   m = lam*m + k*(x - v);  v += m;  s = (v >= th);  v = s ? 0 : v;  out = s
// k = sigmoid(tau_param[0]), lam = lamb[0], th = th[0].
//
// R3 changes vs R2 (40.5us kernel, DRAM traffic 218MB < 268MB app bytes):
//  - loads back to DEFAULT caching (__ldg): let L2 retain x across graph
//    replays (x=134MB vs 126MB L2; ~50MB/replay already served by L2 in R2
//    despite __ldcs fighting retention)
//  - stores stay __stcs (write-once output, evict-first, don't evict x)
//  - block=128 grid=1024 kept (98.8% wave balance)

#ifndef TUNROLL
#define TUNROLL 8
#endif

__global__ __launch_bounds__(128) void mplif_kernel(
    const float4* __restrict__ x4,
    const float* __restrict__ tau_param,
    const float* __restrict__ lamb,
    const float* __restrict__ thr,
    float4* __restrict__ out4,
    int T, int DC /* D/4 */, int lanes /* N*DC */)
{
    int tid = blockIdx.x * blockDim.x + threadIdx.x;
    if (tid >= lanes) return;

    int n = tid / DC;
    int c = tid - n * DC;
    long base = (long)n * T * DC + c;

    const float k   = 1.0f / (1.0f + expf(-tau_param[0]));
    const float lam = lamb[0];
    const float th  = thr[0];

    float4 v = make_float4(0.f, 0.f, 0.f, 0.f);
    float4 m = make_float4(0.f, 0.f, 0.f, 0.f);

    float4 buf[TUNROLL];

    for (int t0 = 0; t0 < T; t0 += TUNROLL) {
        // Batch independent loads (default cache policy: retain x in L2).
        #pragma unroll
        for (int j = 0; j < TUNROLL; j++) {
            buf[j] = __ldg(&x4[base + (long)(t0 + j) * DC]);
        }
        // Serial recurrence on registers.
        #pragma unroll
        for (int j = 0; j < TUNROLL; j++) {
            float4 xv = buf[j];
            float4 s;

            m.x = lam * m.x + k * (xv.x - v.x); v.x += m.x;
            m.y = lam * m.y + k * (xv.y - v.y); v.y += m.y;
            m.z = lam * m.z + k * (xv.z - v.z); v.z += m.z;
            m.w = lam * m.w + k * (xv.w - v.w); v.w += m.w;

            s.x = (v.x >= th) ? 1.0f : 0.0f;
            s.y = (v.y >= th) ? 1.0f : 0.0f;
            s.z = (v.z >= th) ? 1.0f : 0.0f;
            s.w = (v.w >= th) ? 1.0f : 0.0f;

            v.x = (s.x != 0.0f) ? 0.0f : v.x;
            v.y = (s.y != 0.0f) ? 0.0f : v.y;
            v.z = (s.z != 0.0f) ? 0.0f : v.z;
            v.w = (s.w != 0.0f) ? 0.0f : v.w;

            __stcs(&out4[base + (long)(t0 + j) * DC], s);
        }
    }
}

extern "C" void kernel_launch(void* const* d_in, const int* in_sizes, int n_in,
                              void* d_out, int out_size)
{
    const float* x         = (const float*)d_in[0];
    const float* tau_param = (const float*)d_in[1];
    const float* lamb      = (const float*)d_in[2];
    const float* th        = (const float*)d_in[3];
    float* out             = (float*)d_out;

    const int N = 128, T = 64, D = 4096;
    const int DC = D / 4;
    const int lanes = N * DC;

    dim3 block(128);
    dim3 grid((lanes + block.x - 1) / block.x);  // 1024 blocks
    mplif_kernel<<<grid, block>>>((const float4*)x, tau_param, lamb, th,
                                  (float4*)out, T, DC, lanes);
}